// round 1
// baseline (speedup 1.0000x reference)
#include <cuda_runtime.h>
#include <math.h>

#define T_LEN  2048
#define E_DIM  256
#define H_DIM  512
#define K_TAGS 48

// ---------------- scratch (device globals; no allocations allowed) ----------
__device__ float    g_x[T_LEN * E_DIM];            // embedded tokens
__device__ float    g_gx_f[T_LEN * 4 * H_DIM];     // precomputed input gates (fwd)
__device__ float    g_gx_b[T_LEN * 4 * H_DIM];     // precomputed input gates (bwd)
__device__ float    g_h0[T_LEN * 2 * H_DIM];       // layer0 output [fwd|bwd]
__device__ float    g_h1[T_LEN * 2 * H_DIM];       // layer1 output
__device__ float    g_feats[T_LEN * K_TAGS];       // linear output
__device__ unsigned g_ctr[8];                      // barrier counters (layer*2+dir)

// ---------------- tiny init ------------------------------------------------
__global__ void zero_ctrs_kernel() {
    if (threadIdx.x < 8) g_ctr[threadIdx.x] = 0u;
}

// ---------------- embedding gather -----------------------------------------
__global__ void gather_embed_kernel(const int* __restrict__ tok,
                                    const float* __restrict__ embed) {
    int t = blockIdx.x;
    g_x[t * E_DIM + threadIdx.x] =
        embed[(size_t)tok[t] * E_DIM + threadIdx.x];
}

// ---------------- GEMM: C[M,N] = A[M,K]·B[N,K]^T + b1[n] (+ b2[n]) ----------
// 64x64 tile, BK=16, 256 threads, 4x4 per-thread microtile. M%64==0, K%16==0.
__global__ void __launch_bounds__(256) gemm_abt_kernel(
    const float* __restrict__ A, const float* __restrict__ B,
    const float* __restrict__ b1, const float* __restrict__ b2,
    float* __restrict__ C, int M, int N, int K)
{
    __shared__ float As[16][64];
    __shared__ float Bs[16][64];
    const int tid = threadIdx.x;
    const int tx = tid & 15, ty = tid >> 4;
    const int m0 = blockIdx.y * 64, n0 = blockIdx.x * 64;
    const int lr = tid >> 2;          // 0..63  row in tile
    const int lk = (tid & 3) << 2;    // 0,4,8,12

    float acc[4][4] = {};

    for (int kt = 0; kt < K; kt += 16) {
        float4 a4 = *(const float4*)(A + (size_t)(m0 + lr) * K + kt + lk);
        float4 b4 = make_float4(0.f, 0.f, 0.f, 0.f);
        if (n0 + lr < N)
            b4 = *(const float4*)(B + (size_t)(n0 + lr) * K + kt + lk);
        As[lk + 0][lr] = a4.x; As[lk + 1][lr] = a4.y;
        As[lk + 2][lr] = a4.z; As[lk + 3][lr] = a4.w;
        Bs[lk + 0][lr] = b4.x; Bs[lk + 1][lr] = b4.y;
        Bs[lk + 2][lr] = b4.z; Bs[lk + 3][lr] = b4.w;
        __syncthreads();
#pragma unroll
        for (int k = 0; k < 16; k++) {
            float4 av = *(const float4*)&As[k][ty << 2];
            float4 bv = *(const float4*)&Bs[k][tx << 2];
            acc[0][0] = fmaf(av.x, bv.x, acc[0][0]);
            acc[0][1] = fmaf(av.x, bv.y, acc[0][1]);
            acc[0][2] = fmaf(av.x, bv.z, acc[0][2]);
            acc[0][3] = fmaf(av.x, bv.w, acc[0][3]);
            acc[1][0] = fmaf(av.y, bv.x, acc[1][0]);
            acc[1][1] = fmaf(av.y, bv.y, acc[1][1]);
            acc[1][2] = fmaf(av.y, bv.z, acc[1][2]);
            acc[1][3] = fmaf(av.y, bv.w, acc[1][3]);
            acc[2][0] = fmaf(av.z, bv.x, acc[2][0]);
            acc[2][1] = fmaf(av.z, bv.y, acc[2][1]);
            acc[2][2] = fmaf(av.z, bv.z, acc[2][2]);
            acc[2][3] = fmaf(av.z, bv.w, acc[2][3]);
            acc[3][0] = fmaf(av.w, bv.x, acc[3][0]);
            acc[3][1] = fmaf(av.w, bv.y, acc[3][1]);
            acc[3][2] = fmaf(av.w, bv.z, acc[3][2]);
            acc[3][3] = fmaf(av.w, bv.w, acc[3][3]);
        }
        __syncthreads();
    }
#pragma unroll
    for (int j = 0; j < 4; j++) {
        int n = n0 + (tx << 2) + j;
        if (n < N) {
            float bb = b1[n] + (b2 ? b2[n] : 0.f);
#pragma unroll
            for (int i = 0; i < 4; i++)
                C[(size_t)(m0 + (ty << 2) + i) * N + n] = acc[i][j] + bb;
        }
    }
}

// ---------------- persistent bidirectional LSTM recurrence ------------------
// 128 blocks: blocks [0,64) forward, [64,128) backward. Each warp owns one
// h-index (8 per block) and its 4 gate rows in registers (64 floats/lane).
// Per step: stage h(prev) via __ldcg into SMEM, 64 FMA/lane, shfl-reduce,
// lane0 activations + store, then a monotonic atomic barrier per direction.
__global__ void __launch_bounds__(256) lstm_layer_kernel(
    const float* __restrict__ whh_f, const float* __restrict__ whh_b,
    const float* __restrict__ gx_f_, const float* __restrict__ gx_b_,
    float* __restrict__ hout, int layer)
{
    const int dir  = blockIdx.x >> 6;   // 0 fwd, 1 bwd
    const int blk  = blockIdx.x & 63;
    const int warp = threadIdx.x >> 5;
    const int lane = threadIdx.x & 31;
    const int j    = blk * 8 + warp;    // owned h index in [0,512)

    const float* whh = dir ? whh_b : whh_f;
    const float* gx  = dir ? gx_b_ : gx_f_;
    unsigned*    ctr = &g_ctr[layer * 2 + dir];
    float*      hcol = hout + dir * H_DIM;  // column offset in [T, 1024]

    // Load recurrent weights into registers: rows {j, H+j, 2H+j, 3H+j},
    // this lane covers k in [16*lane, 16*lane+16).
    float w[4][16];
#pragma unroll
    for (int g = 0; g < 4; g++) {
        const float* wr = whh + (size_t)(g * H_DIM + j) * H_DIM + lane * 16;
#pragma unroll
        for (int q = 0; q < 4; q++) {
            float4 v = *(const float4*)(wr + q * 4);
            w[g][q * 4 + 0] = v.x; w[g][q * 4 + 1] = v.y;
            w[g][q * 4 + 2] = v.z; w[g][q * 4 + 3] = v.w;
        }
    }

    __shared__ float sh[H_DIM];
    float c = 0.f;  // cell state (meaningful on lane 0 only)

    for (int s = 0; s < T_LEN; s++) {
        const int t = dir ? (T_LEN - 1 - s) : s;

        // Prefetch the precomputed input-gate values (independent of barrier):
        float gxv = 0.f;
        if (lane < 4)
            gxv = gx[(size_t)t * (4 * H_DIM) + lane * H_DIM + j];

        if (s > 0) {
            if (threadIdx.x == 0) {
                const unsigned target = 64u * (unsigned)s;
                while (*(volatile unsigned*)ctr < target) {}
                __threadfence();
            }
            __syncthreads();
            const int tprev = dir ? (t + 1) : (t - 1);
            if (threadIdx.x < 128) {
                float4 v = __ldcg((const float4*)(hcol + (size_t)tprev * (2 * H_DIM))
                                  + threadIdx.x);
                ((float4*)sh)[threadIdx.x] = v;
            }
            __syncthreads();
        } else {
            if (threadIdx.x < 128)
                ((float4*)sh)[threadIdx.x] = make_float4(0.f, 0.f, 0.f, 0.f);
            __syncthreads();
        }

        // 4 gate dot-products over the lane's 16 h values.
        const float* hp = sh + lane * 16;
        float a0 = 0.f, a1 = 0.f, a2 = 0.f, a3 = 0.f;
#pragma unroll
        for (int q = 0; q < 16; q++) {
            float hv = hp[q];
            a0 = fmaf(w[0][q], hv, a0);
            a1 = fmaf(w[1][q], hv, a1);
            a2 = fmaf(w[2][q], hv, a2);
            a3 = fmaf(w[3][q], hv, a3);
        }
#pragma unroll
        for (int off = 16; off; off >>= 1) {
            a0 += __shfl_xor_sync(0xffffffffu, a0, off);
            a1 += __shfl_xor_sync(0xffffffffu, a1, off);
            a2 += __shfl_xor_sync(0xffffffffu, a2, off);
            a3 += __shfl_xor_sync(0xffffffffu, a3, off);
        }
        float gi = a0 + __shfl_sync(0xffffffffu, gxv, 0);
        float gf = a1 + __shfl_sync(0xffffffffu, gxv, 1);
        float gg = a2 + __shfl_sync(0xffffffffu, gxv, 2);
        float go = a3 + __shfl_sync(0xffffffffu, gxv, 3);

        if (lane == 0) {
            float i_ = 1.f / (1.f + expf(-gi));
            float f_ = 1.f / (1.f + expf(-gf));
            float g_ = tanhf(gg);
            float o_ = 1.f / (1.f + expf(-go));
            c = f_ * c + i_ * g_;
            hcol[(size_t)t * (2 * H_DIM) + j] = o_ * tanhf(c);
        }
        __threadfence();
        __syncthreads();
        if (threadIdx.x == 0) atomicAdd(ctr, 1u);
    }
}

// ---------------- CRF forward + gold score (single block) -------------------
__global__ void __launch_bounds__(384) crf_kernel(
    const float* __restrict__ trans, const int* __restrict__ tags,
    const int* __restrict__ seq_len, float* __restrict__ out)
{
    __shared__ float s_tr[K_TAGS * K_TAGS];
    __shared__ float alpha[K_TAGS];
    __shared__ float nalpha[K_TAGS];
    __shared__ float s_ws[12];
    __shared__ float s_score;
    const int tid = threadIdx.x;

    for (int i = tid; i < K_TAGS * K_TAGS; i += 384) s_tr[i] = trans[i];

    // gold score (tg = [START=45] ++ tags)
    float sc = 0.f;
    for (int t = tid; t < T_LEN; t += 384) {
        int cur  = tags[t];
        int prev = (t == 0) ? 45 : tags[t - 1];
        sc += trans[cur * K_TAGS + prev] + g_feats[t * K_TAGS + cur];
    }
#pragma unroll
    for (int off = 16; off; off >>= 1)
        sc += __shfl_xor_sync(0xffffffffu, sc, off);
    if ((tid & 31) == 0) s_ws[tid >> 5] = sc;
    if (tid < K_TAGS) alpha[tid] = (tid == 45) ? 0.f : -100000.f;
    __syncthreads();
    if (tid == 0) {
        float tot = 0.f;
        for (int wd = 0; wd < 12; wd++) tot += s_ws[wd];
        tot += trans[46 * K_TAGS + tags[T_LEN - 1]];  // transition[END, tg[-1]]
        s_score = tot;
    }

    // forward scan: thread (j, g) with g in [0,8) reduces 6 of the 48 i's
    const int j = tid >> 3, g = tid & 7;
    const float* trj = s_tr + j * K_TAGS + g * 6;

    for (int t = 0; t < T_LEN; t++) {
        float v[6];
        float m = -3.4e38f;
#pragma unroll
        for (int q = 0; q < 6; q++) {
            v[q] = alpha[g * 6 + q] + trj[q];
            m = fmaxf(m, v[q]);
        }
#pragma unroll
        for (int off = 4; off; off >>= 1)
            m = fmaxf(m, __shfl_xor_sync(0xffffffffu, m, off));
        float ssum = 0.f;
#pragma unroll
        for (int q = 0; q < 6; q++) ssum += expf(v[q] - m);
#pragma unroll
        for (int off = 4; off; off >>= 1)
            ssum += __shfl_xor_sync(0xffffffffu, ssum, off);
        if (g == 0)
            nalpha[j] = m + logf(ssum) + g_feats[t * K_TAGS + j];
        __syncthreads();
        if (tid < K_TAGS) alpha[tid] = nalpha[tid];
        __syncthreads();
    }

    if (tid == 0) {
        float m = -3.4e38f;
        for (int i = 0; i < K_TAGS; i++)
            m = fmaxf(m, alpha[i] + s_tr[46 * K_TAGS + i]);
        float sum = 0.f;
        for (int i = 0; i < K_TAGS; i++)
            sum += expf(alpha[i] + s_tr[46 * K_TAGS + i] - m);
        float logz = m + logf(sum);
        out[0] = (logz - s_score) / (float)seq_len[0];
    }
}

// ---------------- launcher ---------------------------------------------------
extern "C" void kernel_launch(void* const* d_in, const int* in_sizes, int n_in,
                              void* d_out, int out_size)
{
    const int*   tokens    = (const int*)d_in[0];
    const int*   tags      = (const int*)d_in[1];
    const int*   seqlen    = (const int*)d_in[2];
    const float* embed     = (const float*)d_in[3];
    const float* w_ih_l0_f = (const float*)d_in[4];
    const float* w_hh_l0_f = (const float*)d_in[5];
    const float* b_ih_l0_f = (const float*)d_in[6];
    const float* b_hh_l0_f = (const float*)d_in[7];
    const float* w_ih_l0_b = (const float*)d_in[8];
    const float* w_hh_l0_b = (const float*)d_in[9];
    const float* b_ih_l0_b = (const float*)d_in[10];
    const float* b_hh_l0_b = (const float*)d_in[11];
    const float* w_ih_l1_f = (const float*)d_in[12];
    const float* w_hh_l1_f = (const float*)d_in[13];
    const float* b_ih_l1_f = (const float*)d_in[14];
    const float* b_hh_l1_f = (const float*)d_in[15];
    const float* w_ih_l1_b = (const float*)d_in[16];
    const float* w_hh_l1_b = (const float*)d_in[17];
    const float* b_ih_l1_b = (const float*)d_in[18];
    const float* b_hh_l1_b = (const float*)d_in[19];
    const float* lin_w     = (const float*)d_in[20];
    const float* lin_b     = (const float*)d_in[21];
    const float* transition= (const float*)d_in[22];
    float* out = (float*)d_out;

    float *p_x, *p_gxf, *p_gxb, *p_h0, *p_h1, *p_feats;
    cudaGetSymbolAddress((void**)&p_x,     g_x);
    cudaGetSymbolAddress((void**)&p_gxf,   g_gx_f);
    cudaGetSymbolAddress((void**)&p_gxb,   g_gx_b);
    cudaGetSymbolAddress((void**)&p_h0,    g_h0);
    cudaGetSymbolAddress((void**)&p_h1,    g_h1);
    cudaGetSymbolAddress((void**)&p_feats, g_feats);

    zero_ctrs_kernel<<<1, 32>>>();
    gather_embed_kernel<<<T_LEN, E_DIM>>>(tokens, embed);

    // layer 0 input projections: [2048,256] x [2048,256]^T
    gemm_abt_kernel<<<dim3(32, 32), 256>>>(p_x, w_ih_l0_f, b_ih_l0_f, b_hh_l0_f,
                                           p_gxf, T_LEN, 4 * H_DIM, E_DIM);
    gemm_abt_kernel<<<dim3(32, 32), 256>>>(p_x, w_ih_l0_b, b_ih_l0_b, b_hh_l0_b,
                                           p_gxb, T_LEN, 4 * H_DIM, E_DIM);
    // layer 0 recurrence
    lstm_layer_kernel<<<128, 256>>>(w_hh_l0_f, w_hh_l0_b, p_gxf, p_gxb, p_h0, 0);

    // layer 1 input projections: [2048,1024] x [2048,1024]^T
    gemm_abt_kernel<<<dim3(32, 32), 256>>>(p_h0, w_ih_l1_f, b_ih_l1_f, b_hh_l1_f,
                                           p_gxf, T_LEN, 4 * H_DIM, 2 * H_DIM);
    gemm_abt_kernel<<<dim3(32, 32), 256>>>(p_h0, w_ih_l1_b, b_ih_l1_b, b_hh_l1_b,
                                           p_gxb, T_LEN, 4 * H_DIM, 2 * H_DIM);
    // layer 1 recurrence
    lstm_layer_kernel<<<128, 256>>>(w_hh_l1_f, w_hh_l1_b, p_gxf, p_gxb, p_h1, 1);

    // final linear: [2048,1024] x [48,1024]^T
    gemm_abt_kernel<<<dim3(1, 32), 256>>>(p_h1, lin_w, lin_b, nullptr,
                                          p_feats, T_LEN, K_TAGS, 2 * H_DIM);

    // CRF forward + gold score -> scalar
    crf_kernel<<<1, 384>>>(transition, tags, seqlen, out);
}

// round 2
// speedup vs baseline: 1.8854x; 1.8854x over previous
#include <cuda_runtime.h>
#include <math.h>

#define T_LEN  2048
#define E_DIM  256
#define H_DIM  512
#define K_TAGS 48

// ---------------- scratch (device globals; no allocations allowed) ----------
__device__ float    g_x[T_LEN * E_DIM];            // embedded tokens
__device__ float    g_gx_f[T_LEN * 4 * H_DIM];     // precomputed input gates (fwd)
__device__ float    g_gx_b[T_LEN * 4 * H_DIM];     // precomputed input gates (bwd)
__device__ float    g_h0[T_LEN * 2 * H_DIM];       // layer0 output [fwd|bwd] (plain)
__device__ float    g_h1[T_LEN * 2 * H_DIM];       // layer1 output (plain)
__device__ float    g_feats[T_LEN * K_TAGS];       // linear output
// tagged {h, t+1} pairs for the intra-recurrence producer->consumer handoff
__device__ unsigned long long g_p0[T_LEN * 2 * H_DIM];
__device__ unsigned long long g_p1[T_LEN * 2 * H_DIM];

// ---------------- clear tag pairs (must run each launch) ---------------------
__global__ void clear_pairs_kernel() {
    int i = blockIdx.x * blockDim.x + threadIdx.x;   // 2M threads
    g_p0[i] = 0ull;
    g_p1[i] = 0ull;
}

// ---------------- embedding gather -----------------------------------------
__global__ void gather_embed_kernel(const int* __restrict__ tok,
                                    const float* __restrict__ embed) {
    int t = blockIdx.x;
    g_x[t * E_DIM + threadIdx.x] =
        embed[(size_t)tok[t] * E_DIM + threadIdx.x];
}

// ---------------- GEMM: C[M,N] = A[M,K]·B[N,K]^T + b1[n] (+ b2[n]) ----------
// 64x64 tile, BK=16, 256 threads, 4x4 per-thread microtile. M%64==0, K%16==0.
__global__ void __launch_bounds__(256) gemm_abt_kernel(
    const float* __restrict__ A, const float* __restrict__ B,
    const float* __restrict__ b1, const float* __restrict__ b2,
    float* __restrict__ C, int M, int N, int K)
{
    __shared__ float As[16][64];
    __shared__ float Bs[16][64];
    const int tid = threadIdx.x;
    const int tx = tid & 15, ty = tid >> 4;
    const int m0 = blockIdx.y * 64, n0 = blockIdx.x * 64;
    const int lr = tid >> 2;          // 0..63  row in tile
    const int lk = (tid & 3) << 2;    // 0,4,8,12

    float acc[4][4] = {};

    for (int kt = 0; kt < K; kt += 16) {
        float4 a4 = *(const float4*)(A + (size_t)(m0 + lr) * K + kt + lk);
        float4 b4 = make_float4(0.f, 0.f, 0.f, 0.f);
        if (n0 + lr < N)
            b4 = *(const float4*)(B + (size_t)(n0 + lr) * K + kt + lk);
        As[lk + 0][lr] = a4.x; As[lk + 1][lr] = a4.y;
        As[lk + 2][lr] = a4.z; As[lk + 3][lr] = a4.w;
        Bs[lk + 0][lr] = b4.x; Bs[lk + 1][lr] = b4.y;
        Bs[lk + 2][lr] = b4.z; Bs[lk + 3][lr] = b4.w;
        __syncthreads();
#pragma unroll
        for (int k = 0; k < 16; k++) {
            float4 av = *(const float4*)&As[k][ty << 2];
            float4 bv = *(const float4*)&Bs[k][tx << 2];
            acc[0][0] = fmaf(av.x, bv.x, acc[0][0]);
            acc[0][1] = fmaf(av.x, bv.y, acc[0][1]);
            acc[0][2] = fmaf(av.x, bv.z, acc[0][2]);
            acc[0][3] = fmaf(av.x, bv.w, acc[0][3]);
            acc[1][0] = fmaf(av.y, bv.x, acc[1][0]);
            acc[1][1] = fmaf(av.y, bv.y, acc[1][1]);
            acc[1][2] = fmaf(av.y, bv.z, acc[1][2]);
            acc[1][3] = fmaf(av.y, bv.w, acc[1][3]);
            acc[2][0] = fmaf(av.z, bv.x, acc[2][0]);
            acc[2][1] = fmaf(av.z, bv.y, acc[2][1]);
            acc[2][2] = fmaf(av.z, bv.z, acc[2][2]);
            acc[2][3] = fmaf(av.z, bv.w, acc[2][3]);
            acc[3][0] = fmaf(av.w, bv.x, acc[3][0]);
            acc[3][1] = fmaf(av.w, bv.y, acc[3][1]);
            acc[3][2] = fmaf(av.w, bv.z, acc[3][2]);
            acc[3][3] = fmaf(av.w, bv.w, acc[3][3]);
        }
        __syncthreads();
    }
#pragma unroll
    for (int j = 0; j < 4; j++) {
        int n = n0 + (tx << 2) + j;
        if (n < N) {
            float bb = b1[n] + (b2 ? b2[n] : 0.f);
#pragma unroll
            for (int i = 0; i < 4; i++)
                C[(size_t)(m0 + (ty << 2) + i) * N + n] = acc[i][j] + bb;
        }
    }
}

// ---------------- persistent bidirectional LSTM recurrence ------------------
// 128 blocks: [0,64) fwd, [64,128) bwd. Each warp owns one h-index j
// (8 per block); weights in registers laid out so SMEM reads are
// conflict-free float4s. Sync via tagged 8B {h, t+1} pairs: producers
// st.global.cg.b64, consumers spin on ld.global.cg.b64. No fences/atomics.
__global__ void __launch_bounds__(256) lstm_layer_kernel(
    const float* __restrict__ whh_f, const float* __restrict__ whh_b,
    const float* __restrict__ gx_f_, const float* __restrict__ gx_b_,
    float* __restrict__ hout, unsigned long long* __restrict__ pairs)
{
    const int dir  = blockIdx.x >> 6;   // 0 fwd, 1 bwd
    const int blk  = blockIdx.x & 63;
    const int warp = threadIdx.x >> 5;
    const int lane = threadIdx.x & 31;
    const int j    = blk * 8 + warp;    // owned h index in [0,512)

    const float* whh = dir ? whh_b : whh_f;
    const float* gx  = dir ? gx_b_ : gx_f_;
    float*      hcol = hout + dir * H_DIM;                 // plain [T,1024]
    unsigned long long* pcol = pairs + dir * H_DIM;        // tagged [T,1024]

    // Registers: w[g][q*4+r] = whh[g*512+j][q*128 + lane*4 + r]
    float w[4][16];
#pragma unroll
    for (int g = 0; g < 4; g++) {
        const float* wr = whh + (size_t)(g * H_DIM + j) * H_DIM;
#pragma unroll
        for (int q = 0; q < 4; q++) {
            float4 v = *(const float4*)(wr + q * 128 + lane * 4);
            w[g][q * 4 + 0] = v.x; w[g][q * 4 + 1] = v.y;
            w[g][q * 4 + 2] = v.z; w[g][q * 4 + 3] = v.w;
        }
    }

    __shared__ float sh[H_DIM];
    float c = 0.f;  // replicated across lanes (all lanes compute identically)

    for (int s = 0; s < T_LEN; s++) {
        const int t = dir ? (T_LEN - 1 - s) : s;

        // Prefetch input-gate values (independent of the poll below).
        float gxv = 0.f;
        if (lane < 4)
            gxv = gx[(size_t)t * (4 * H_DIM) + lane * H_DIM + j];

        if (s > 0) {
            const int tprev = dir ? (t + 1) : (t - 1);
            const unsigned long long* row = pcol + (size_t)tprev * (2 * H_DIM);
            const unsigned expect = (unsigned)(tprev + 1);
            // 256 threads x 2 pairs each = 512 h values
            {
                const unsigned long long* a0 = row + threadIdx.x;
                unsigned long long v;
                do {
                    asm volatile("ld.global.cg.b64 %0, [%1];"
                                 : "=l"(v) : "l"(a0) : "memory");
                } while ((unsigned)(v >> 32) != expect);
                sh[threadIdx.x] = __uint_as_float((unsigned)v);
                const unsigned long long* a1 = row + threadIdx.x + 256;
                do {
                    asm volatile("ld.global.cg.b64 %0, [%1];"
                                 : "=l"(v) : "l"(a1) : "memory");
                } while ((unsigned)(v >> 32) != expect);
                sh[threadIdx.x + 256] = __uint_as_float((unsigned)v);
            }
            __syncthreads();
        } else {
            if (threadIdx.x < 128)
                ((float4*)sh)[threadIdx.x] = make_float4(0.f, 0.f, 0.f, 0.f);
            __syncthreads();
        }

        // 4 gate dot-products; conflict-free float4 SMEM reads.
        float a0 = 0.f, a1 = 0.f, a2 = 0.f, a3 = 0.f;
#pragma unroll
        for (int q = 0; q < 4; q++) {
            float4 hv = *(const float4*)&sh[q * 128 + lane * 4];
            a0 = fmaf(w[0][q*4+0], hv.x, a0); a0 = fmaf(w[0][q*4+1], hv.y, a0);
            a0 = fmaf(w[0][q*4+2], hv.z, a0); a0 = fmaf(w[0][q*4+3], hv.w, a0);
            a1 = fmaf(w[1][q*4+0], hv.x, a1); a1 = fmaf(w[1][q*4+1], hv.y, a1);
            a1 = fmaf(w[1][q*4+2], hv.z, a1); a1 = fmaf(w[1][q*4+3], hv.w, a1);
            a2 = fmaf(w[2][q*4+0], hv.x, a2); a2 = fmaf(w[2][q*4+1], hv.y, a2);
            a2 = fmaf(w[2][q*4+2], hv.z, a2); a2 = fmaf(w[2][q*4+3], hv.w, a2);
            a3 = fmaf(w[3][q*4+0], hv.x, a3); a3 = fmaf(w[3][q*4+1], hv.y, a3);
            a3 = fmaf(w[3][q*4+2], hv.z, a3); a3 = fmaf(w[3][q*4+3], hv.w, a3);
        }
#pragma unroll
        for (int off = 16; off; off >>= 1) {
            a0 += __shfl_xor_sync(0xffffffffu, a0, off);
            a1 += __shfl_xor_sync(0xffffffffu, a1, off);
            a2 += __shfl_xor_sync(0xffffffffu, a2, off);
            a3 += __shfl_xor_sync(0xffffffffu, a3, off);
        }

        // Parallel activations on lanes 0..3 (i, f, g, o). Uniform sigmoid
        // path; tanh(v) = 2*sigmoid(2v) - 1.
        float act = 0.f;
        if (lane < 4) {
            float v = (lane == 0 ? a0 : lane == 1 ? a1 : lane == 2 ? a2 : a3) + gxv;
            float vv = (lane == 2) ? 2.f * v : v;
            float sgm = 1.f / (1.f + expf(-vv));
            act = (lane == 2) ? (2.f * sgm - 1.f) : sgm;
        }
        float i_ = __shfl_sync(0xffffffffu, act, 0);
        float f_ = __shfl_sync(0xffffffffu, act, 1);
        float g_ = __shfl_sync(0xffffffffu, act, 2);
        float o_ = __shfl_sync(0xffffffffu, act, 3);

        c = f_ * c + i_ * g_;
        float tc = 2.f / (1.f + expf(-2.f * c)) - 1.f;   // tanh(c)
        float h  = o_ * tc;

        if (lane == 0) {
            hcol[(size_t)t * (2 * H_DIM) + j] = h;       // plain (for GEMMs)
            unsigned long long pk =
                ((unsigned long long)(unsigned)(t + 1) << 32) |
                (unsigned long long)__float_as_uint(h);
            asm volatile("st.global.cg.b64 [%0], %1;"
                         :: "l"(pcol + (size_t)t * (2 * H_DIM) + j), "l"(pk)
                         : "memory");
        }
        __syncthreads();   // protect sh before next iteration's refill
    }
}

// ---------------- CRF forward + gold score (single block) -------------------
__global__ void __launch_bounds__(384) crf_kernel(
    const float* __restrict__ trans, const int* __restrict__ tags,
    const int* __restrict__ seq_len, float* __restrict__ out)
{
    __shared__ float s_tr[K_TAGS * K_TAGS];
    __shared__ float alpha[K_TAGS];
    __shared__ float nalpha[K_TAGS];
    __shared__ float s_ws[12];
    __shared__ float s_score;
    const int tid = threadIdx.x;

    for (int i = tid; i < K_TAGS * K_TAGS; i += 384) s_tr[i] = trans[i];

    // gold score (tg = [START=45] ++ tags)
    float sc = 0.f;
    for (int t = tid; t < T_LEN; t += 384) {
        int cur  = tags[t];
        int prev = (t == 0) ? 45 : tags[t - 1];
        sc += trans[cur * K_TAGS + prev] + g_feats[t * K_TAGS + cur];
    }
#pragma unroll
    for (int off = 16; off; off >>= 1)
        sc += __shfl_xor_sync(0xffffffffu, sc, off);
    if ((tid & 31) == 0) s_ws[tid >> 5] = sc;
    if (tid < K_TAGS) alpha[tid] = (tid == 45) ? 0.f : -100000.f;
    __syncthreads();
    if (tid == 0) {
        float tot = 0.f;
        for (int wd = 0; wd < 12; wd++) tot += s_ws[wd];
        tot += trans[46 * K_TAGS + tags[T_LEN - 1]];  // transition[END, tg[-1]]
        s_score = tot;
    }

    // forward scan: thread (j, g) with g in [0,8) reduces 6 of the 48 i's
    const int j = tid >> 3, g = tid & 7;
    const float* trj = s_tr + j * K_TAGS + g * 6;

    for (int t = 0; t < T_LEN; t++) {
        float v[6];
        float m = -3.4e38f;
#pragma unroll
        for (int q = 0; q < 6; q++) {
            v[q] = alpha[g * 6 + q] + trj[q];
            m = fmaxf(m, v[q]);
        }
#pragma unroll
        for (int off = 4; off; off >>= 1)
            m = fmaxf(m, __shfl_xor_sync(0xffffffffu, m, off));
        float ssum = 0.f;
#pragma unroll
        for (int q = 0; q < 6; q++) ssum += expf(v[q] - m);
#pragma unroll
        for (int off = 4; off; off >>= 1)
            ssum += __shfl_xor_sync(0xffffffffu, ssum, off);
        if (g == 0)
            nalpha[j] = m + logf(ssum) + g_feats[t * K_TAGS + j];
        __syncthreads();
        if (tid < K_TAGS) alpha[tid] = nalpha[tid];
        __syncthreads();
    }

    if (tid == 0) {
        float m = -3.4e38f;
        for (int i = 0; i < K_TAGS; i++)
            m = fmaxf(m, alpha[i] + s_tr[46 * K_TAGS + i]);
        float sum = 0.f;
        for (int i = 0; i < K_TAGS; i++)
            sum += expf(alpha[i] + s_tr[46 * K_TAGS + i] - m);
        float logz = m + logf(sum);
        out[0] = (logz - s_score) / (float)seq_len[0];
    }
}

// ---------------- launcher ---------------------------------------------------
extern "C" void kernel_launch(void* const* d_in, const int* in_sizes, int n_in,
                              void* d_out, int out_size)
{
    const int*   tokens    = (const int*)d_in[0];
    const int*   tags      = (const int*)d_in[1];
    const int*   seqlen    = (const int*)d_in[2];
    const float* embed     = (const float*)d_in[3];
    const float* w_ih_l0_f = (const float*)d_in[4];
    const float* w_hh_l0_f = (const float*)d_in[5];
    const float* b_ih_l0_f = (const float*)d_in[6];
    const float* b_hh_l0_f = (const float*)d_in[7];
    const float* w_ih_l0_b = (const float*)d_in[8];
    const float* w_hh_l0_b = (const float*)d_in[9];
    const float* b_ih_l0_b = (const float*)d_in[10];
    const float* b_hh_l0_b = (const float*)d_in[11];
    const float* w_ih_l1_f = (const float*)d_in[12];
    const float* w_hh_l1_f = (const float*)d_in[13];
    const float* b_ih_l1_f = (const float*)d_in[14];
    const float* b_hh_l1_f = (const float*)d_in[15];
    const float* w_ih_l1_b = (const float*)d_in[16];
    const float* w_hh_l1_b = (const float*)d_in[17];
    const float* b_ih_l1_b = (const float*)d_in[18];
    const float* b_hh_l1_b = (const float*)d_in[19];
    const float* lin_w     = (const float*)d_in[20];
    const float* lin_b     = (const float*)d_in[21];
    const float* transition= (const float*)d_in[22];
    float* out = (float*)d_out;

    float *p_x, *p_h0, *p_h1, *p_feats, *p_gxf, *p_gxb;
    unsigned long long *p_pr0, *p_pr1;
    cudaGetSymbolAddress((void**)&p_x,     g_x);
    cudaGetSymbolAddress((void**)&p_gxf,   g_gx_f);
    cudaGetSymbolAddress((void**)&p_gxb,   g_gx_b);
    cudaGetSymbolAddress((void**)&p_h0,    g_h0);
    cudaGetSymbolAddress((void**)&p_h1,    g_h1);
    cudaGetSymbolAddress((void**)&p_feats, g_feats);
    cudaGetSymbolAddress((void**)&p_pr0,   g_p0);
    cudaGetSymbolAddress((void**)&p_pr1,   g_p1);

    // clear handoff tags (2M entries per array)
    clear_pairs_kernel<<<(T_LEN * 2 * H_DIM) / 512, 512>>>();
    gather_embed_kernel<<<T_LEN, E_DIM>>>(tokens, embed);

    // layer 0 input projections: [2048,256] x [2048,256]^T
    gemm_abt_kernel<<<dim3(32, 32), 256>>>(p_x, w_ih_l0_f, b_ih_l0_f, b_hh_l0_f,
                                           p_gxf, T_LEN, 4 * H_DIM, E_DIM);
    gemm_abt_kernel<<<dim3(32, 32), 256>>>(p_x, w_ih_l0_b, b_ih_l0_b, b_hh_l0_b,
                                           p_gxb, T_LEN, 4 * H_DIM, E_DIM);
    // layer 0 recurrence
    lstm_layer_kernel<<<128, 256>>>(w_hh_l0_f, w_hh_l0_b, p_gxf, p_gxb, p_h0, p_pr0);

    // layer 1 input projections: [2048,1024] x [2048,1024]^T
    gemm_abt_kernel<<<dim3(32, 32), 256>>>(p_h0, w_ih_l1_f, b_ih_l1_f, b_hh_l1_f,
                                           p_gxf, T_LEN, 4 * H_DIM, 2 * H_DIM);
    gemm_abt_kernel<<<dim3(32, 32), 256>>>(p_h0, w_ih_l1_b, b_ih_l1_b, b_hh_l1_b,
                                           p_gxb, T_LEN, 4 * H_DIM, 2 * H_DIM);
    // layer 1 recurrence
    lstm_layer_kernel<<<128, 256>>>(w_hh_l1_f, w_hh_l1_b, p_gxf, p_gxb, p_h1, p_pr1);

    // final linear: [2048,1024] x [48,1024]^T
    gemm_abt_kernel<<<dim3(1, 32), 256>>>(p_h1, lin_w, lin_b, nullptr,
                                          p_feats, T_LEN, K_TAGS, 2 * H_DIM);

    // CRF forward + gold score -> scalar
    crf_kernel<<<1, 384>>>(transition, tags, seqlen, out);
}

// round 3
// speedup vs baseline: 1.9131x; 1.0147x over previous
#include <cuda_runtime.h>
#include <math.h>

#define T_LEN  2048
#define E_DIM  256
#define H_DIM  512
#define K_TAGS 48

// ---------------- scratch (device globals; no allocations allowed) ----------
__device__ float    g_x[T_LEN * E_DIM];            // embedded tokens
__device__ float    g_gx_f[T_LEN * 4 * H_DIM];     // precomputed input gates (fwd)
__device__ float    g_gx_b[T_LEN * 4 * H_DIM];     // precomputed input gates (bwd)
__device__ float    g_h0[T_LEN * 2 * H_DIM];       // layer0 output [fwd|bwd] (plain)
__device__ float    g_h1[T_LEN * 2 * H_DIM];       // layer1 output (plain)
__device__ float    g_feats[T_LEN * K_TAGS];       // linear output
// tagged {h, t+1} pairs for the intra-recurrence producer->consumer handoff
__device__ unsigned long long g_p0[T_LEN * 2 * H_DIM];
__device__ unsigned long long g_p1[T_LEN * 2 * H_DIM];

// ---------------- clear tag pairs (must run each launch) ---------------------
__global__ void clear_pairs_kernel() {
    int i = blockIdx.x * blockDim.x + threadIdx.x;   // 2M threads
    g_p0[i] = 0ull;
    g_p1[i] = 0ull;
}

// ---------------- embedding gather -----------------------------------------
__global__ void gather_embed_kernel(const int* __restrict__ tok,
                                    const float* __restrict__ embed) {
    int t = blockIdx.x;
    g_x[t * E_DIM + threadIdx.x] =
        embed[(size_t)tok[t] * E_DIM + threadIdx.x];
}

// ---------------- GEMM: C[M,N] = A[M,K]·B[N,K]^T + b1[n] (+ b2[n]) ----------
// 128x128 tile, BK=8, 256 threads, 8x8 per-thread microtile.
// Requires M%128==0, K%8==0. N may be ragged (guarded).
__global__ void __launch_bounds__(256) gemm_abt_kernel(
    const float* __restrict__ A, const float* __restrict__ B,
    const float* __restrict__ b1, const float* __restrict__ b2,
    float* __restrict__ C, int M, int N, int K)
{
    __shared__ float As[8][128];
    __shared__ float Bs[8][128];
    const int tid = threadIdx.x;
    const int tx = tid & 15, ty = tid >> 4;          // 16 x 16 thread grid
    const int m0 = blockIdx.y * 128, n0 = blockIdx.x * 128;
    const int lr = tid >> 1;                         // 0..127 row in tile
    const int lk = (tid & 1) * 4;                    // 0 or 4

    float acc[8][8] = {};

    for (int kt = 0; kt < K; kt += 8) {
        float4 a4 = *(const float4*)(A + (size_t)(m0 + lr) * K + kt + lk);
        float4 b4 = make_float4(0.f, 0.f, 0.f, 0.f);
        if (n0 + lr < N)
            b4 = *(const float4*)(B + (size_t)(n0 + lr) * K + kt + lk);
        As[lk + 0][lr] = a4.x; As[lk + 1][lr] = a4.y;
        As[lk + 2][lr] = a4.z; As[lk + 3][lr] = a4.w;
        Bs[lk + 0][lr] = b4.x; Bs[lk + 1][lr] = b4.y;
        Bs[lk + 2][lr] = b4.z; Bs[lk + 3][lr] = b4.w;
        __syncthreads();
#pragma unroll
        for (int k = 0; k < 8; k++) {
            float4 av0 = *(const float4*)&As[k][ty * 8];
            float4 av1 = *(const float4*)&As[k][ty * 8 + 4];
            float4 bv0 = *(const float4*)&Bs[k][tx * 8];
            float4 bv1 = *(const float4*)&Bs[k][tx * 8 + 4];
            float a8[8] = {av0.x, av0.y, av0.z, av0.w, av1.x, av1.y, av1.z, av1.w};
            float b8[8] = {bv0.x, bv0.y, bv0.z, bv0.w, bv1.x, bv1.y, bv1.z, bv1.w};
#pragma unroll
            for (int i = 0; i < 8; i++)
#pragma unroll
                for (int j = 0; j < 8; j++)
                    acc[i][j] = fmaf(a8[i], b8[j], acc[i][j]);
        }
        __syncthreads();
    }
#pragma unroll
    for (int j = 0; j < 8; j++) {
        int n = n0 + tx * 8 + j;
        if (n < N) {
            float bb = b1[n] + (b2 ? b2[n] : 0.f);
#pragma unroll
            for (int i = 0; i < 8; i++)
                C[(size_t)(m0 + ty * 8 + i) * N + n] = acc[i][j] + bb;
        }
    }
}

// ---------------- persistent bidirectional LSTM recurrence ------------------
// 128 blocks: [0,64) fwd, [64,128) bwd. Each warp owns one h-index j
// (8 per block); recurrent weights live in registers as packed f32x2 so the
// gate dot products run on the FFMA2 path. Handoff is tagged 8B {h, t+1}
// pairs: producers st.global.cg.b64, consumers spin on ld.global.cg.v2.u64.
__global__ void __launch_bounds__(256) lstm_layer_kernel(
    const float* __restrict__ whh_f, const float* __restrict__ whh_b,
    const float* __restrict__ gx_f_, const float* __restrict__ gx_b_,
    float* __restrict__ hout, unsigned long long* __restrict__ pairs)
{
    const int dir  = blockIdx.x >> 6;   // 0 fwd, 1 bwd
    const int blk  = blockIdx.x & 63;
    const int warp = threadIdx.x >> 5;
    const int lane = threadIdx.x & 31;
    const int j    = blk * 8 + warp;    // owned h index in [0,512)

    const float* whh = dir ? whh_b : whh_f;
    const float* gx  = dir ? gx_b_ : gx_f_;
    float*      hcol = hout + dir * H_DIM;                 // plain [T,1024]
    unsigned long long* pcol = pairs + dir * H_DIM;        // tagged [T,1024]

    // Packed weights: w2[g][q2] covers h-indices {q*128 + lane*4 ..+3}
    // for q = q2>>1, pair = q2&1.
    unsigned long long w2[4][8];
#pragma unroll
    for (int g = 0; g < 4; g++) {
        const float* wr = whh + (size_t)(g * H_DIM + j) * H_DIM;
#pragma unroll
        for (int q = 0; q < 4; q++) {
            float4 v = *(const float4*)(wr + q * 128 + lane * 4);
            asm("mov.b64 %0, {%1, %2};" : "=l"(w2[g][q * 2 + 0])
                : "r"(__float_as_uint(v.x)), "r"(__float_as_uint(v.y)));
            asm("mov.b64 %0, {%1, %2};" : "=l"(w2[g][q * 2 + 1])
                : "r"(__float_as_uint(v.z)), "r"(__float_as_uint(v.w)));
        }
    }

    __shared__ float sh[2][H_DIM];
    // zero both buffers (step 0 reads sh[0])
    if (threadIdx.x < 128) {
        ((float4*)sh[0])[threadIdx.x] = make_float4(0.f, 0.f, 0.f, 0.f);
        ((float4*)sh[1])[threadIdx.x] = make_float4(0.f, 0.f, 0.f, 0.f);
    }
    __syncthreads();

    float c = 0.f;  // replicated across lanes

    for (int s = 0; s < T_LEN; s++) {
        const int t   = dir ? (T_LEN - 1 - s) : s;
        const int buf = s & 1;

        // Prefetch input-gate values (independent of the poll below).
        float gxv = 0.f;
        if (lane < 4)
            gxv = gx[(size_t)t * (4 * H_DIM) + lane * H_DIM + j];

        if (s > 0) {
            const int tprev = dir ? (t + 1) : (t - 1);
            const unsigned long long* row = pcol + (size_t)tprev * (2 * H_DIM);
            const unsigned expect = (unsigned)(tprev + 1);
            // each thread polls 2 adjacent pairs with one 16B load
            const unsigned long long* ap = row + 2 * threadIdx.x;
            unsigned long long v0, v1;
            do {
                asm volatile("ld.global.cg.v2.u64 {%0, %1}, [%2];"
                             : "=l"(v0), "=l"(v1) : "l"(ap) : "memory");
            } while ((unsigned)(v0 >> 32) != expect ||
                     (unsigned)(v1 >> 32) != expect);
            sh[buf][2 * threadIdx.x + 0] = __uint_as_float((unsigned)v0);
            sh[buf][2 * threadIdx.x + 1] = __uint_as_float((unsigned)v1);
            __syncthreads();   // single sync: double buffer removes WAR hazard
        }

        // 4 gate dot-products on the packed-f32x2 path.
        unsigned long long acc2[4] = {0ull, 0ull, 0ull, 0ull};
#pragma unroll
        for (int q = 0; q < 4; q++) {
            float4 hv = *(const float4*)&sh[buf][q * 128 + lane * 4];
            unsigned long long h01, h23;
            asm("mov.b64 %0, {%1, %2};" : "=l"(h01)
                : "r"(__float_as_uint(hv.x)), "r"(__float_as_uint(hv.y)));
            asm("mov.b64 %0, {%1, %2};" : "=l"(h23)
                : "r"(__float_as_uint(hv.z)), "r"(__float_as_uint(hv.w)));
#pragma unroll
            for (int g = 0; g < 4; g++) {
                asm("fma.rn.f32x2 %0, %1, %2, %0;"
                    : "+l"(acc2[g]) : "l"(w2[g][q * 2 + 0]), "l"(h01));
                asm("fma.rn.f32x2 %0, %1, %2, %0;"
                    : "+l"(acc2[g]) : "l"(w2[g][q * 2 + 1]), "l"(h23));
            }
        }
        float a0, a1, a2, a3;
        {
            unsigned lo, hi;
            asm("mov.b64 {%0, %1}, %2;" : "=r"(lo), "=r"(hi) : "l"(acc2[0]));
            a0 = __uint_as_float(lo) + __uint_as_float(hi);
            asm("mov.b64 {%0, %1}, %2;" : "=r"(lo), "=r"(hi) : "l"(acc2[1]));
            a1 = __uint_as_float(lo) + __uint_as_float(hi);
            asm("mov.b64 {%0, %1}, %2;" : "=r"(lo), "=r"(hi) : "l"(acc2[2]));
            a2 = __uint_as_float(lo) + __uint_as_float(hi);
            asm("mov.b64 {%0, %1}, %2;" : "=r"(lo), "=r"(hi) : "l"(acc2[3]));
            a3 = __uint_as_float(lo) + __uint_as_float(hi);
        }
#pragma unroll
        for (int off = 16; off; off >>= 1) {
            a0 += __shfl_xor_sync(0xffffffffu, a0, off);
            a1 += __shfl_xor_sync(0xffffffffu, a1, off);
            a2 += __shfl_xor_sync(0xffffffffu, a2, off);
            a3 += __shfl_xor_sync(0xffffffffu, a3, off);
        }

        // Parallel activations on lanes 0..3 (i, f, g, o); tanh(v)=2sig(2v)-1.
        float act = 0.f;
        if (lane < 4) {
            float v = (lane == 0 ? a0 : lane == 1 ? a1 : lane == 2 ? a2 : a3) + gxv;
            float vv = (lane == 2) ? 2.f * v : v;
            float sgm = 1.f / (1.f + __expf(-vv));
            act = (lane == 2) ? (2.f * sgm - 1.f) : sgm;
        }
        float i_ = __shfl_sync(0xffffffffu, act, 0);
        float f_ = __shfl_sync(0xffffffffu, act, 1);
        float g_ = __shfl_sync(0xffffffffu, act, 2);
        float o_ = __shfl_sync(0xffffffffu, act, 3);

        c = f_ * c + i_ * g_;
        float tc = 2.f / (1.f + __expf(-2.f * c)) - 1.f;   // tanh(c)
        float h  = o_ * tc;

        if (lane == 0) {
            hcol[(size_t)t * (2 * H_DIM) + j] = h;       // plain (for GEMMs)
            unsigned long long pk =
                ((unsigned long long)(unsigned)(t + 1) << 32) |
                (unsigned long long)__float_as_uint(h);
            asm volatile("st.global.cg.b64 [%0], %1;"
                         :: "l"(pcol + (size_t)t * (2 * H_DIM) + j), "l"(pk)
                         : "memory");
        }
    }
}

// ---------------- CRF forward + gold score (single block) -------------------
__global__ void __launch_bounds__(384) crf_kernel(
    const float* __restrict__ trans, const int* __restrict__ tags,
    const int* __restrict__ seq_len, float* __restrict__ out)
{
    __shared__ float s_tr[K_TAGS * K_TAGS];
    __shared__ float alpha[K_TAGS];
    __shared__ float nalpha[K_TAGS];
    __shared__ float s_ws[12];
    __shared__ float s_score;
    const int tid = threadIdx.x;

    for (int i = tid; i < K_TAGS * K_TAGS; i += 384) s_tr[i] = trans[i];

    // gold score (tg = [START=45] ++ tags)
    float sc = 0.f;
    for (int t = tid; t < T_LEN; t += 384) {
        int cur  = tags[t];
        int prev = (t == 0) ? 45 : tags[t - 1];
        sc += trans[cur * K_TAGS + prev] + g_feats[t * K_TAGS + cur];
    }
#pragma unroll
    for (int off = 16; off; off >>= 1)
        sc += __shfl_xor_sync(0xffffffffu, sc, off);
    if ((tid & 31) == 0) s_ws[tid >> 5] = sc;
    if (tid < K_TAGS) alpha[tid] = (tid == 45) ? 0.f : -100000.f;
    __syncthreads();
    if (tid == 0) {
        float tot = 0.f;
        for (int wd = 0; wd < 12; wd++) tot += s_ws[wd];
        tot += trans[46 * K_TAGS + tags[T_LEN - 1]];  // transition[END, tg[-1]]
        s_score = tot;
    }

    // forward scan: thread (j, g) with g in [0,8) reduces 6 of the 48 i's
    const int j = tid >> 3, g = tid & 7;
    const float* trj = s_tr + j * K_TAGS + g * 6;

    for (int t = 0; t < T_LEN; t++) {
        float v[6];
        float m = -3.4e38f;
#pragma unroll
        for (int q = 0; q < 6; q++) {
            v[q] = alpha[g * 6 + q] + trj[q];
            m = fmaxf(m, v[q]);
        }
#pragma unroll
        for (int off = 4; off; off >>= 1)
            m = fmaxf(m, __shfl_xor_sync(0xffffffffu, m, off));
        float ssum = 0.f;
#pragma unroll
        for (int q = 0; q < 6; q++) ssum += expf(v[q] - m);
#pragma unroll
        for (int off = 4; off; off >>= 1)
            ssum += __shfl_xor_sync(0xffffffffu, ssum, off);
        if (g == 0)
            nalpha[j] = m + logf(ssum) + g_feats[t * K_TAGS + j];
        __syncthreads();
        if (tid < K_TAGS) alpha[tid] = nalpha[tid];
        __syncthreads();
    }

    if (tid == 0) {
        float m = -3.4e38f;
        for (int i = 0; i < K_TAGS; i++)
            m = fmaxf(m, alpha[i] + s_tr[46 * K_TAGS + i]);
        float sum = 0.f;
        for (int i = 0; i < K_TAGS; i++)
            sum += expf(alpha[i] + s_tr[46 * K_TAGS + i] - m);
        float logz = m + logf(sum);
        out[0] = (logz - s_score) / (float)seq_len[0];
    }
}

// ---------------- launcher ---------------------------------------------------
extern "C" void kernel_launch(void* const* d_in, const int* in_sizes, int n_in,
                              void* d_out, int out_size)
{
    const int*   tokens    = (const int*)d_in[0];
    const int*   tags      = (const int*)d_in[1];
    const int*   seqlen    = (const int*)d_in[2];
    const float* embed     = (const float*)d_in[3];
    const float* w_ih_l0_f = (const float*)d_in[4];
    const float* w_hh_l0_f = (const float*)d_in[5];
    const float* b_ih_l0_f = (const float*)d_in[6];
    const float* b_hh_l0_f = (const float*)d_in[7];
    const float* w_ih_l0_b = (const float*)d_in[8];
    const float* w_hh_l0_b = (const float*)d_in[9];
    const float* b_ih_l0_b = (const float*)d_in[10];
    const float* b_hh_l0_b = (const float*)d_in[11];
    const float* w_ih_l1_f = (const float*)d_in[12];
    const float* w_hh_l1_f = (const float*)d_in[13];
    const float* b_ih_l1_f = (const float*)d_in[14];
    const float* b_hh_l1_f = (const float*)d_in[15];
    const float* w_ih_l1_b = (const float*)d_in[16];
    const float* w_hh_l1_b = (const float*)d_in[17];
    const float* b_ih_l1_b = (const float*)d_in[18];
    const float* b_hh_l1_b = (const float*)d_in[19];
    const float* lin_w     = (const float*)d_in[20];
    const float* lin_b     = (const float*)d_in[21];
    const float* transition= (const float*)d_in[22];
    float* out = (float*)d_out;

    float *p_x, *p_h0, *p_h1, *p_feats, *p_gxf, *p_gxb;
    unsigned long long *p_pr0, *p_pr1;
    cudaGetSymbolAddress((void**)&p_x,     g_x);
    cudaGetSymbolAddress((void**)&p_gxf,   g_gx_f);
    cudaGetSymbolAddress((void**)&p_gxb,   g_gx_b);
    cudaGetSymbolAddress((void**)&p_h0,    g_h0);
    cudaGetSymbolAddress((void**)&p_h1,    g_h1);
    cudaGetSymbolAddress((void**)&p_feats, g_feats);
    cudaGetSymbolAddress((void**)&p_pr0,   g_p0);
    cudaGetSymbolAddress((void**)&p_pr1,   g_p1);

    // clear handoff tags (2M entries per array)
    clear_pairs_kernel<<<(T_LEN * 2 * H_DIM) / 512, 512>>>();
    gather_embed_kernel<<<T_LEN, E_DIM>>>(tokens, embed);

    // layer 0 input projections: [2048,256] x [2048,256]^T
    gemm_abt_kernel<<<dim3(16, 16), 256>>>(p_x, w_ih_l0_f, b_ih_l0_f, b_hh_l0_f,
                                           p_gxf, T_LEN, 4 * H_DIM, E_DIM);
    gemm_abt_kernel<<<dim3(16, 16), 256>>>(p_x, w_ih_l0_b, b_ih_l0_b, b_hh_l0_b,
                                           p_gxb, T_LEN, 4 * H_DIM, E_DIM);
    // layer 0 recurrence
    lstm_layer_kernel<<<128, 256>>>(w_hh_l0_f, w_hh_l0_b, p_gxf, p_gxb, p_h0, p_pr0);

    // layer 1 input projections: [2048,1024] x [2048,1024]^T
    gemm_abt_kernel<<<dim3(16, 16), 256>>>(p_h0, w_ih_l1_f, b_ih_l1_f, b_hh_l1_f,
                                           p_gxf, T_LEN, 4 * H_DIM, 2 * H_DIM);
    gemm_abt_kernel<<<dim3(16, 16), 256>>>(p_h0, w_ih_l1_b, b_ih_l1_b, b_hh_l1_b,
                                           p_gxb, T_LEN, 4 * H_DIM, 2 * H_DIM);
    // layer 1 recurrence
    lstm_layer_kernel<<<128, 256>>>(w_hh_l1_f, w_hh_l1_b, p_gxf, p_gxb, p_h1, p_pr1);

    // final linear: [2048,1024] x [48,1024]^T
    gemm_abt_kernel<<<dim3(1, 16), 256>>>(p_h1, lin_w, lin_b, nullptr,
                                          p_feats, T_LEN, K_TAGS, 2 * H_DIM);

    // CRF forward + gold score -> scalar
    crf_kernel<<<1, 384>>>(transition, tags, seqlen, out);
}